// round 14
// baseline (speedup 1.0000x reference)
#include <cuda_runtime.h>

#define H    4096
#define IN   512
#define OUT  64
#define NJ4  (H / 4)       // 1024 float4 columns
#define GY   296           // k-stripes
#define NIB  128           // i2h blocks   (bids 0..127)
#define NSB  592           // stripe blocks (bids 128..719)
#define NRB  128           // reducer blocks (bids 720..847)
#define NOB  64            // out-head blocks (bids 848..911)

// Device-global scratch (no allocations allowed).
__device__ float4   g_part[(size_t)GY * NJ4];  // ~4.85 MB
__device__ float    g_init[H];                 // bias + i2h
__device__ float    g_x[H];
__device__ unsigned g_done;    // +NSB per launch (stripe blocks)
__device__ unsigned g_rtkt;    // +NRB per launch (reducer tickets)
__device__ unsigned g_done2;   // +NRB per launch (reducers -> x ready)
__device__ unsigned g_otkt;    // +NOB per launch (out tickets)

// ---------------------------------------------------------------------------
// Kernel 1, four block roles by bid (monotonic-ticket sync, graph-safe):
//  [0,128)   i2h:      g_init = b_i2h + inp @ W_i2h.T  (finish fast, free slots)
//  [128,720) stripe:   GEMV partials (R8 pattern: 8-wide, v8 evict_last hebb)
//  [720,848) reducer:  wait stripes -> x = relu(g_init + sum partials)
//  [848,912) out-head: wait reducers -> out = tanh(x @ W_h2o.T + b)
// ---------------------------------------------------------------------------
__global__ void __launch_bounds__(256)
k_main(const float* __restrict__ hidden, const float* __restrict__ hebb,
       const float* __restrict__ w,      const float* __restrict__ plas,
       const float* __restrict__ inp,    const float* __restrict__ W_i2h,
       const float* __restrict__ b_i2h,  const float* __restrict__ W_h2o,
       const float* __restrict__ b_h2o,  float* __restrict__ x_out,
       float* __restrict__ out) {
    int b = blockIdx.x, t = threadIdx.x;

    if (b < NIB) {
        // ================= i2h: 32 rows per block, warp per row x4 ========
        int wrp = t >> 5, lane = t & 31;
        const float4* in4 = (const float4*)inp;
#pragma unroll
        for (int rr = 0; rr < 4; ++rr) {
            int row = b * 32 + wrp * 4 + rr;
            const float4* wr = (const float4*)(W_i2h + (size_t)row * IN);
            float d = 0.f;
#pragma unroll
            for (int q = 0; q < (IN / 4) / 32; ++q) {
                float4 aa = wr[lane + q * 32];
                float4 bb = in4[lane + q * 32];
                d += aa.x * bb.x + aa.y * bb.y + aa.z * bb.z + aa.w * bb.w;
            }
#pragma unroll
            for (int o = 16; o; o >>= 1) d += __shfl_down_sync(0xffffffffu, d, o);
            if (lane == 0) g_init[row] = d + b_i2h[row];
        }
        return;
    }

    if (b < NIB + NSB) {
        // ================= stripe: GEMV partial ==========================
        int sb = b - NIB;
        int stripe = sb >> 1;
        int j8 = (sb & 1) * 256 + t;           // 0..511
        int k0 = (stripe * H) / GY;
        int k1 = ((stripe + 1) * H) / GY;

        const float4* w4 = (const float4*)w;
        const float4* p4 = (const float4*)plas;
        const float4* h4 = (const float4*)hebb;

        float4 acc0 = make_float4(0.f, 0.f, 0.f, 0.f);
        float4 acc1 = make_float4(0.f, 0.f, 0.f, 0.f);
        size_t fbase = (size_t)j8 * 2;
#pragma unroll 4
        for (int r = k0; r < k1; ++r) {
            size_t idx = (size_t)r * NJ4 + fbase;
            float hk = __ldg(hidden + r);
            float4 a0 = w4[idx], a1 = w4[idx + 1];
            float4 b0 = p4[idx], b1 = p4[idx + 1];
            float4 c0, c1;
            asm volatile(
                "ld.global.nc.L2::evict_last.v8.b32 "
                "{%0,%1,%2,%3,%4,%5,%6,%7}, [%8];"
                : "=f"(c0.x), "=f"(c0.y), "=f"(c0.z), "=f"(c0.w),
                  "=f"(c1.x), "=f"(c1.y), "=f"(c1.z), "=f"(c1.w)
                : "l"(h4 + idx));
            acc0.x += hk * fmaf(b0.x, c0.x, a0.x);
            acc0.y += hk * fmaf(b0.y, c0.y, a0.y);
            acc0.z += hk * fmaf(b0.z, c0.z, a0.z);
            acc0.w += hk * fmaf(b0.w, c0.w, a0.w);
            acc1.x += hk * fmaf(b1.x, c1.x, a1.x);
            acc1.y += hk * fmaf(b1.y, c1.y, a1.y);
            acc1.z += hk * fmaf(b1.z, c1.z, a1.z);
            acc1.w += hk * fmaf(b1.w, c1.w, a1.w);
        }
        size_t o = (size_t)stripe * NJ4 + fbase;
        g_part[o]     = acc0;
        g_part[o + 1] = acc1;
        __threadfence();
        __syncthreads();
        if (t == 0) atomicAdd(&g_done, 1u);
        return;
    }

    if (b < NIB + NSB + NRB) {
        // ================= reducer: finalize x ===========================
        __shared__ float4 sp[32][8];
        __shared__ float4 stot[8];
        int rb = b - NIB - NSB;          // 0..127
        int j4base = rb * 8;             // 8 f4 cols = 32 scalar cols

        if (t == 0) {
            unsigned tk = atomicAdd(&g_rtkt, 1u);
            unsigned target = (tk / NRB + 1u) * NSB;
            volatile unsigned* p = &g_done;
            while (*p < target) __nanosleep(64);
        }
        __syncthreads();
        __threadfence();

        int j4loc = t & 7;
        int grp   = t >> 3;              // 0..31
        float4 acc = make_float4(0.f, 0.f, 0.f, 0.f);
#pragma unroll
        for (int q = 0; q < (GY + 31) / 32; ++q) {
            int kb = grp + 32 * q;
            if (kb < GY) {
                float4 v = g_part[(size_t)kb * NJ4 + j4base + j4loc];
                acc.x += v.x; acc.y += v.y; acc.z += v.z; acc.w += v.w;
            }
        }
        sp[grp][j4loc] = acc;
        __syncthreads();
        if (t < 8) {
            float4 t4 = make_float4(0.f, 0.f, 0.f, 0.f);
#pragma unroll
            for (int g = 0; g < 32; ++g) {
                float4 v = sp[g][t];
                t4.x += v.x; t4.y += v.y; t4.z += v.z; t4.w += v.w;
            }
            stot[t] = t4;
        }
        __syncthreads();
        if (t < 32) {
            int col  = t;
            int jl   = col >> 2, comp = col & 3;
            float4 t4 = stot[jl];
            float part = (comp == 0) ? t4.x : (comp == 1) ? t4.y
                       : (comp == 2) ? t4.z : t4.w;
            int j = j4base * 4 + col;
            float v = fmaxf(part + g_init[j], 0.f);
            g_x[j]   = v;
            x_out[j] = v;
        }
        __threadfence();
        __syncthreads();
        if (t == 0) atomicAdd(&g_done2, 1u);
        return;
    }

    // ================= out-head: needs full x ============================
    {
        __shared__ float red[8];
        int o = b - NIB - NSB - NRB;     // 0..63
        if (t == 0) {
            unsigned tk = atomicAdd(&g_otkt, 1u);
            unsigned target = (tk / NOB + 1u) * NRB;
            volatile unsigned* p = &g_done2;
            while (*p < target) __nanosleep(64);
        }
        __syncthreads();
        __threadfence();

        const float4* wr = (const float4*)(W_h2o + (size_t)o * H);
        const float4* x4 = (const float4*)g_x;
        float acc = 0.f;
#pragma unroll
        for (int q = 0; q < NJ4 / 256; ++q) {
            float4 aa = wr[t + q * 256];
            float4 bb = x4[t + q * 256];
            acc += aa.x * bb.x + aa.y * bb.y + aa.z * bb.z + aa.w * bb.w;
        }
#pragma unroll
        for (int s = 16; s; s >>= 1) acc += __shfl_down_sync(0xffffffffu, acc, s);
        if ((t & 31) == 0) red[t >> 5] = acc;
        __syncthreads();
        if (t == 0) {
            float v = red[0] + red[1] + red[2] + red[3] +
                      red[4] + red[5] + red[6] + red[7];
            out[o] = tanhf(v + b_h2o[o]);
        }
    }
}

// ---------------------------------------------------------------------------
// Kernel 2: pure hebb update — R1's measured-20.8us configuration
// (plain float4 load/store, no branch, regs ~26, occ ~79%).
// ---------------------------------------------------------------------------
__global__ void __launch_bounds__(256)
k_hebb(const float* __restrict__ hidden,
       const float* __restrict__ hebb,
       const float* __restrict__ learn_p,
       float* __restrict__ hebb_out) {
    int idx = blockIdx.x * blockDim.x + threadIdx.x;  // float4 index
    int k   = idx >> 10;
    int jc  = idx & 1023;
    float learn = __ldg(learn_p);
    float hk    = __ldg(hidden + k);
    float4 hb = ((const float4*)hebb)[idx];
    float4 xv = ((const float4*)g_x)[jc];
    float a = 1.f - learn;
    float s = learn * hk;
    float4 o;
    o.x = fmaf(a, hb.x, s * xv.x);
    o.y = fmaf(a, hb.y, s * xv.y);
    o.z = fmaf(a, hb.z, s * xv.z);
    o.w = fmaf(a, hb.w, s * xv.w);
    ((float4*)hebb_out)[idx] = o;
}

// ---------------------------------------------------------------------------
// Inputs: 0 inp, 1 hidden, 2 hebb, 3 W_i2h, 4 b_i2h, 5 w, 6 plas,
//         7 learn, 8 W_h2o, 9 b_h2o
// Output: [out(64) | x(4096) | hebb_new(16777216)]
// ---------------------------------------------------------------------------
extern "C" void kernel_launch(void* const* d_in, const int* in_sizes, int n_in,
                              void* d_out, int out_size) {
    const float* inp    = (const float*)d_in[0];
    const float* hidden = (const float*)d_in[1];
    const float* hebb   = (const float*)d_in[2];
    const float* W_i2h  = (const float*)d_in[3];
    const float* b_i2h  = (const float*)d_in[4];
    const float* w      = (const float*)d_in[5];
    const float* plas   = (const float*)d_in[6];
    const float* learn  = (const float*)d_in[7];
    const float* W_h2o  = (const float*)d_in[8];
    const float* b_h2o  = (const float*)d_in[9];

    float* out      = (float*)d_out;
    float* x_out    = out + OUT;
    float* hebb_out = out + OUT + H;

    // Kernel 1: i2h + GEMV partials + x-finalize + out-head (role-split grid)
    k_main<<<NIB + NSB + NRB + NOB, 256>>>(hidden, hebb, w, plas, inp,
                                           W_i2h, b_i2h, W_h2o, b_h2o,
                                           x_out, out);

    // Kernel 2: pure hebb update
    k_hebb<<<(H * H / 4) / 256, 256>>>(hidden, hebb, learn, hebb_out);
}